// round 15
// baseline (speedup 1.0000x reference)
#include <cuda_runtime.h>
#include <cuda_fp16.h>
#include <math.h>
#include <stdint.h>

typedef unsigned long long u64;
typedef unsigned int u32;

#define Bn 16
#define Cn 64
#define Hn 128
#define Wn 128
#define HWn (Hn*Wn)
#define IMG (Cn*HWn)

// scratch
__device__ float g_md[4][Cn];
__device__ float g_ms[4][Cn];
// fp16 weights: [layer][tap][kind: 0=w, 1=w*md_ci][o*64+ci]
__device__ __half g_wt[4][9][2][Cn*Cn];
// fp16 wc for final 1x1: [o][k=256]
__device__ __half g_wc[64*256];
// fp16 NHWC features: input (converted x0) + 4 conv layer outputs
__device__ __half g16in[(u64)Bn*HWn*Cn];
__device__ __half g16[4][(u64)Bn*HWn*Cn];

// ---------------- smem layout for conv_mma (bytes) ---------------------------
// input: 3 halo rows (y-1,y,y+1), [row][xp 0..129][ci 0..63], 144B per xp
#define PX_XP_STRIDE 144
#define PX_ROW_STRIDE (130*PX_XP_STRIDE)       // 18720
#define OFF_PX 0
#define PX_BYTES (3*PX_ROW_STRIDE)             // 56160
// weights triple-buffered per-tap: [buf 0..2][kind 0..1][o], 144B per o
#define OFF_W  PX_BYTES
#define W_O_STRIDE 144
#define W_KIND_STRIDE (64*W_O_STRIDE)          // 9216
#define W_BUF_STRIDE (2*W_KIND_STRIDE)         // 18432
#define OFF_MD (OFF_W + 3*W_BUF_STRIDE)        // 111456
#define OFF_MS (OFF_MD + 256)
#define SMEM_MMA (OFF_MS + 256)                // 111968  (2 CTAs/SM)

// ---------------- smem layout for final_mma (bytes) --------------------------
#define FA_PX_STRIDE 144
#define FA_BUF_STRIDE (256*FA_PX_STRIDE)       // 36864
#define F_OFF_A 0
#define F_OFF_B (2*FA_BUF_STRIDE)              // 73728
#define FB_O_STRIDE 528
#define SMEM_FIN (F_OFF_B + 64*FB_O_STRIDE)    // 107520

// ---------------- warp-mma helpers (baseline PTX, no 'a' features) -----------
__device__ __forceinline__ void mma16816(float* c, const u32* a, u32 b0, u32 b1){
    asm("mma.sync.aligned.m16n8k16.row.col.f32.f16.f16.f32 "
        "{%0,%1,%2,%3},{%4,%5,%6,%7},{%8,%9},{%0,%1,%2,%3};"
        : "+f"(c[0]),"+f"(c[1]),"+f"(c[2]),"+f"(c[3])
        : "r"(a[0]),"r"(a[1]),"r"(a[2]),"r"(a[3]), "r"(b0),"r"(b1));
}
__device__ __forceinline__ void ldmat4(u32* r, u32 addr){
    asm volatile("ldmatrix.sync.aligned.m8n8.x4.shared.b16 {%0,%1,%2,%3},[%4];"
                 : "=r"(r[0]),"=r"(r[1]),"=r"(r[2]),"=r"(r[3]) : "r"(addr));
}
__device__ __forceinline__ void cp16(u32 dst, const void* src){
    asm volatile("cp.async.cg.shared.global [%0], [%1], 16;"
                 :: "r"(dst), "l"(src) : "memory");
}
__device__ __forceinline__ void cp_commit(){
    asm volatile("cp.async.commit_group;" ::: "memory");
}
template<int N>
__device__ __forceinline__ void cp_wait(){
    asm volatile("cp.async.wait_group %0;" :: "n"(N) : "memory");
}

// ---------------------------------------------------------------------------
// Gumbel-softmax channel mask
// ---------------------------------------------------------------------------
__global__ void mask_kernel(const float* __restrict__ gum,
                            const float* __restrict__ par,
                            float* __restrict__ out_tail)
{
    int c = threadIdx.x;
    if (c >= Cn) return;
#pragma unroll
    for (int l = 0; l < 4; ++l) {
        int i0 = c*8 + l*2;
        float g0 = -logf(-logf(gum[i0]));
        float g1 = -logf(-logf(gum[i0+1]));
        float l0 = par[i0]   + g0;
        float l1 = par[i0+1] + g1;
        float e  = expf(l1 - l0);
        float m0 = 1.0f/(1.0f+e);
        float m1 = e/(1.0f+e);
        g_md[l][c] = m0;
        g_ms[l][c] = m1;
        out_tail[i0]   = m0;
        out_tail[i0+1] = m1;
    }
}

// ---------------------------------------------------------------------------
// Weight prep: fp16 W and W*md_ci per tap, plus fp16 wc for the final 1x1.
// ---------------------------------------------------------------------------
__global__ void prep_kernel(const float* __restrict__ w0, const float* __restrict__ w1,
                            const float* __restrict__ w2, const float* __restrict__ w3,
                            const float* __restrict__ wc)
{
    int idx = blockIdx.x*256 + threadIdx.x;
    if (idx < 4*9*Cn*Cn) {
        int l  = idx / (9*Cn*Cn);
        int r  = idx - l*(9*Cn*Cn);
        int t  = r / (Cn*Cn);
        int oc = r - t*(Cn*Cn);
        int ci = oc & 63;
        const float* ws = (l==0) ? w0 : (l==1) ? w1 : (l==2) ? w2 : w3;
        float v = ws[(oc >> 6)*(Cn*9) + ci*9 + t];
        g_wt[l][t][0][oc] = __float2half(v);
        g_wt[l][t][1][oc] = __float2half(v * g_md[l][ci]);
    } else {
        int i2 = idx - 4*9*Cn*Cn;
        if (i2 < 64*256) g_wc[i2] = __float2half(wc[i2]);
    }
}

// ---------------------------------------------------------------------------
// x0 NCHW fp32 -> NHWC fp16 (one image row per CTA)
// ---------------------------------------------------------------------------
__global__ void __launch_bounds__(256)
cvt_kernel(const float* __restrict__ x0)
{
    __shared__ __half s[128*65];
    const int y = blockIdx.x, b = blockIdx.y;
    const int tid = threadIdx.x;
#pragma unroll
    for (int it = 0; it < 32; ++it) {
        int idx = tid + it*256;
        int ci = idx >> 7, x = idx & 127;
        s[x*65 + ci] = __float2half(x0[(b*Cn + ci)*HWn + y*Wn + x]);
    }
    __syncthreads();
    __half* dst = g16in + ((u64)b*HWn + (u64)y*Wn)*Cn;
#pragma unroll
    for (int it = 0; it < 32; ++it) {
        int idx = tid + it*256;
        int x = idx >> 6, ci = idx & 63;
        dst[(u64)x*Cn + ci] = s[x*65 + ci];
    }
}

// ---------------------------------------------------------------------------
// Warp-MMA conv layer: mma.sync m16n8k16 fp16, cp.async NHWC A staging.
// 256-thread CTA, one output row (M=128 px), 2 CTAs/SM. Triple-buffered
// per-tap weights -> ONE __syncthreads per tap (buf b rewritten at tap t+3,
// ordered after tap-t reads by the two intervening barriers).
//  DUAL=false: out = relu( F * (ms_o*spa + md_o) )
//  DUAL=true : out = relu( D * md_o*(1-spa) + F*spa ), D = A x (W*diag(md))
// ---------------------------------------------------------------------------
template<bool DUAL>
__global__ void __launch_bounds__(256, 2)
conv_mma(const float* __restrict__ spa, int layer)
{
    extern __shared__ __align__(128) char sm[];
    const u32 smb  = (u32)__cvta_generic_to_shared(sm);
    const int tid  = threadIdx.x;
    const int lane = tid & 31;
    const int wid  = tid >> 5;

    const int y = blockIdx.x;
    const int b = blockIdx.y;
    const int kinds = DUAL ? 2 : 1;

    float* s_md = (float*)(sm + OFF_MD);
    float* s_ms = (float*)(sm + OFF_MS);
    if (tid < Cn) { s_md[tid] = g_md[layer][tid]; s_ms[tid] = g_ms[layer][tid]; }

    // weight stager: tap t -> buffer t%3 (16B cp.async chunks)
    auto stageW = [&](int t){
        const u32 dst0 = smb + OFF_W + (u32)(t % 3)*W_BUF_STRIDE;
        const int n16 = kinds * 512;
#pragma unroll 1
        for (int idx = tid; idx < n16; idx += 256) {
            int kind = idx >> 9, i = idx & 511;
            int o = i >> 3, seg = i & 7;
            cp16(dst0 + (u32)(kind*W_KIND_STRIDE + o*W_O_STRIDE + seg*16),
                 (const char*)&g_wt[layer][t][kind][0] + o*128 + seg*16);
        }
        cp_commit();
    };

    stageW(0);   // group: W0

    // ---- stage input: 3 halo rows (y-1..y+1), fp16 NHWC via cp.async -------
    {
        const __half* src16 = (layer == 0)
            ? (g16in + (u64)b*((u64)HWn*Cn))
            : (g16[layer-1] + (u64)b*((u64)HWn*Cn));
        if (tid < 96) {        // zero x-halo columns (xp=0, xp=129) x 3 rows
            int r = tid / 32, col = (tid >> 4) & 1, i = tid & 15;
            *(u64*)(sm + OFF_PX + r*PX_ROW_STRIDE
                    + (col ? 129*PX_XP_STRIDE : 0) + i*8) = 0;
        }
#pragma unroll
        for (int r = 0; r < 3; ++r) {
            const int yy = y - 1 + r;
            if ((unsigned)yy < Hn) {
                const __half* rowsrc = src16 + (u64)yy*Wn*Cn;
#pragma unroll
                for (int it = 0; it < 4; ++it) {
                    int idx = tid + it*256;        // 1024 chunks: 128px x 8seg
                    int px = idx >> 3, seg = idx & 7;
                    cp16(smb + OFF_PX + (u32)(r*PX_ROW_STRIDE
                             + (px+1)*PX_XP_STRIDE + seg*16),
                         (const char*)(rowsrc + px*Cn) + seg*16);
                }
            } else {
#pragma unroll 1
                for (int i = tid; i < 130*16; i += 256)
                    *(u64*)(sm + OFF_PX + r*PX_ROW_STRIDE
                            + (i >> 4)*PX_XP_STRIDE + (i & 15)*8) = 0;
            }
        }
        cp_commit();   // group: A
    }
    stageW(1);         // group: W1

    // warp tile: mq = M quarter (32 px), nq = N half (32 och)
    const int mq    = wid & 3;
    const int nq    = wid >> 2;
    const int xbase = mq << 5;
    const int obase = nq << 5;

    const u32 a_lane = (u32)((lane & 15)*PX_XP_STRIDE + ((lane >> 4) << 4));
    const int lrow = lane & 7, lgrp = lane >> 3;
    const u32 b_lane = (u32)(((lgrp >> 1)*8 + lrow)*W_O_STRIDE + (lgrp & 1)*16);

    float accF[2][4][4], accD[2][4][4];
#pragma unroll
    for (int mt = 0; mt < 2; ++mt)
#pragma unroll
        for (int n = 0; n < 4; ++n)
#pragma unroll
            for (int j = 0; j < 4; ++j) {
                accF[mt][n][j] = 0.f;
                if (DUAL) accD[mt][n][j] = 0.f;
            }

#pragma unroll 1
    for (int t = 0; t < 9; ++t) {
        // pending groups before wait: [Wt, (A if t==0), Wt+1]  -> wait Wt (+A)
        if (t < 8) cp_wait<1>(); else cp_wait<0>();
        __syncthreads();
        if (t < 7) stageW(t + 2);   // writes buf (t+2)%3 == (t-1)%3: safe, its
                                    // readers finished before the sync above

        const int ky = t/3, kx = t - (t/3)*3;
        const u32 abase = smb + OFF_PX
                        + (u32)(ky*PX_ROW_STRIDE)
                        + (u32)((kx + xbase)*PX_XP_STRIDE)
                        + a_lane;
        const u32 wbase = smb + OFF_W + (u32)(t % 3)*W_BUF_STRIDE
                        + (u32)(obase*W_O_STRIDE) + b_lane;

#pragma unroll
        for (int kk = 0; kk < 4; ++kk) {
            u32 Ah[2][4];
            ldmat4(Ah[0], abase + kk*32);
            ldmat4(Ah[1], abase + 16*PX_XP_STRIDE + kk*32);
#pragma unroll
            for (int ntp = 0; ntp < 2; ++ntp) {
                const u32 wb = wbase + (u32)(ntp*16*W_O_STRIDE + kk*32);
                const int n0 = ntp*2, n1 = n0 + 1;
                if (DUAL) {
                    u32 Bh[4], Bm[4];
                    ldmat4(Bh, wb);
                    ldmat4(Bm, wb + W_KIND_STRIDE);
                    mma16816(accF[0][n0], Ah[0], Bh[0], Bh[1]);
                    mma16816(accF[0][n1], Ah[0], Bh[2], Bh[3]);
                    mma16816(accF[1][n0], Ah[1], Bh[0], Bh[1]);
                    mma16816(accF[1][n1], Ah[1], Bh[2], Bh[3]);
                    mma16816(accD[0][n0], Ah[0], Bm[0], Bm[1]);
                    mma16816(accD[0][n1], Ah[0], Bm[2], Bm[3]);
                    mma16816(accD[1][n0], Ah[1], Bm[0], Bm[1]);
                    mma16816(accD[1][n1], Ah[1], Bm[2], Bm[3]);
                } else {
                    u32 Bh[4];
                    ldmat4(Bh, wb);
                    mma16816(accF[0][n0], Ah[0], Bh[0], Bh[1]);
                    mma16816(accF[0][n1], Ah[0], Bh[2], Bh[3]);
                    mma16816(accF[1][n0], Ah[1], Bh[0], Bh[1]);
                    mma16816(accF[1][n1], Ah[1], Bh[2], Bh[3]);
                }
            }
        }
    }

    // ---- fused gate + ReLU epilogue: fp16 NHWC ----
    const int g  = lane >> 2;
    const int t4 = lane & 3;
    __half* o16 = g16[layer] + ((u64)b*HWn + (u64)y*Wn)*Cn;

#pragma unroll
    for (int mt = 0; mt < 2; ++mt) {
        const int xA = xbase + mt*16 + g;
        const int xB = xA + 8;
        const float spA = spa[b*HWn + y*Wn + xA];
        const float spB = spa[b*HWn + y*Wn + xB];
#pragma unroll
        for (int nt = 0; nt < 4; ++nt) {
            const int o0 = obase + nt*8 + 2*t4, o1 = o0 + 1;
            float r0, r1, r2, r3;
            if (!DUAL) {
                r0 = accF[mt][nt][0] * (s_ms[o0]*spA + s_md[o0]);
                r1 = accF[mt][nt][1] * (s_ms[o1]*spA + s_md[o1]);
                r2 = accF[mt][nt][2] * (s_ms[o0]*spB + s_md[o0]);
                r3 = accF[mt][nt][3] * (s_ms[o1]*spB + s_md[o1]);
            } else {
                r0 = accD[mt][nt][0]*s_md[o0]*(1.f-spA) + accF[mt][nt][0]*spA;
                r1 = accD[mt][nt][1]*s_md[o1]*(1.f-spA) + accF[mt][nt][1]*spA;
                r2 = accD[mt][nt][2]*s_md[o0]*(1.f-spB) + accF[mt][nt][2]*spB;
                r3 = accD[mt][nt][3]*s_md[o1]*(1.f-spB) + accF[mt][nt][3]*spB;
            }
            r0 = fmaxf(r0, 0.f); r1 = fmaxf(r1, 0.f);
            r2 = fmaxf(r2, 0.f); r3 = fmaxf(r3, 0.f);
            *(__half2*)(o16 + (u64)xA*Cn + o0) = __floats2half2_rn(r0, r1);
            *(__half2*)(o16 + (u64)xB*Cn + o0) = __floats2half2_rn(r2, r3);
        }
    }
}

// ---------------------------------------------------------------------------
// Final 1x1 conv on tensor cores: M=256 px, N=64, K=256 (4 NHWC layers).
// ---------------------------------------------------------------------------
__global__ void __launch_bounds__(512, 1)
final_mma(const float* __restrict__ bc, float* __restrict__ outp)
{
    extern __shared__ __align__(128) char sm[];
    const u32 smb  = (u32)__cvta_generic_to_shared(sm);
    const int tid  = threadIdx.x;
    const int lane = tid & 31;
    const int wid  = tid >> 5;

    const int px0 = blockIdx.x * 256;
    const int b   = blockIdx.y;

#pragma unroll
    for (int it = 0; it < 4; ++it) {
        int idx = tid + it*512;
        int o = idx >> 5, seg = idx & 31;
        cp16(smb + F_OFF_B + (u32)(o*FB_O_STRIDE + seg*16),
             (const char*)(g_wc + o*256) + seg*16);
    }
    cp_commit();

    auto stageA = [&](int l, int bi){
        const __half* src = g16[l] + ((u64)b*HWn + (u64)px0)*Cn;
        const u32 dst = smb + F_OFF_A + (u32)bi*FA_BUF_STRIDE;
#pragma unroll
        for (int it = 0; it < 4; ++it) {
            int idx = tid + it*512;
            int px = idx >> 3, seg = idx & 7;
            cp16(dst + (u32)(px*FA_PX_STRIDE + seg*16),
                 (const char*)(src + (u64)px*Cn) + seg*16);
        }
        cp_commit();
    };
    stageA(0, 0);

    const int mq = wid & 7;
    const int nq = wid >> 3;
    const int obase = nq << 5;

    const u32 a_lane = (u32)((lane & 15)*FA_PX_STRIDE + ((lane >> 4) << 4));
    const int lrow = lane & 7, lgrp = lane >> 3;
    const u32 b_lane = (u32)(((lgrp >> 1)*8 + lrow)*FB_O_STRIDE + (lgrp & 1)*16);

    float acc[2][4][4];
#pragma unroll
    for (int mt = 0; mt < 2; ++mt)
#pragma unroll
        for (int n = 0; n < 4; ++n)
#pragma unroll
            for (int j = 0; j < 4; ++j) acc[mt][n][j] = 0.f;

#pragma unroll 1
    for (int l = 0; l < 4; ++l) {
        const int bi = l & 1;
        if (l < 3) stageA(l+1, bi^1);
        if (l < 3) cp_wait<1>(); else cp_wait<0>();
        __syncthreads();

        const u32 abase = smb + F_OFF_A + (u32)bi*FA_BUF_STRIDE
                        + (u32)(mq*32*FA_PX_STRIDE) + a_lane;
        const u32 wbase = smb + F_OFF_B + (u32)(obase*FB_O_STRIDE)
                        + (u32)(l*128) + b_lane;
#pragma unroll
        for (int kk = 0; kk < 4; ++kk) {
            u32 Ah[2][4];
            ldmat4(Ah[0], abase + kk*32);
            ldmat4(Ah[1], abase + 16*FA_PX_STRIDE + kk*32);
#pragma unroll
            for (int ntp = 0; ntp < 2; ++ntp) {
                const u32 wb = wbase + (u32)(ntp*16*FB_O_STRIDE + kk*32);
                const int n0 = ntp*2, n1 = n0 + 1;
                u32 Bh[4];
                ldmat4(Bh, wb);
                mma16816(acc[0][n0], Ah[0], Bh[0], Bh[1]);
                mma16816(acc[0][n1], Ah[0], Bh[2], Bh[3]);
                mma16816(acc[1][n0], Ah[1], Bh[0], Bh[1]);
                mma16816(acc[1][n1], Ah[1], Bh[2], Bh[3]);
            }
        }
        __syncthreads();
    }

    const int g  = lane >> 2;
    const int t4 = lane & 3;
    float* ob = outp + (u64)b*IMG + px0;

#pragma unroll
    for (int mt = 0; mt < 2; ++mt) {
        const int xA = mq*32 + mt*16 + g;
        const int xB = xA + 8;
#pragma unroll
        for (int nt = 0; nt < 4; ++nt) {
            const int o0 = obase + nt*8 + 2*t4, o1 = o0 + 1;
            ob[o0*HWn + xA] = acc[mt][nt][0] + bc[o0];
            ob[o1*HWn + xA] = acc[mt][nt][1] + bc[o1];
            ob[o0*HWn + xB] = acc[mt][nt][2] + bc[o0];
            ob[o1*HWn + xB] = acc[mt][nt][3] + bc[o1];
        }
    }
}

// ---------------------------------------------------------------------------
extern "C" void kernel_launch(void* const* d_in, const int* in_sizes, int n_in,
                              void* d_out, int out_size)
{
    const float* x0  = (const float*)d_in[0];
    const float* spa = (const float*)d_in[1];
    const float* gum = (const float*)d_in[2];
    const float* par = (const float*)d_in[3];
    const float* w0  = (const float*)d_in[4];
    const float* w1  = (const float*)d_in[5];
    const float* w2  = (const float*)d_in[6];
    const float* w3  = (const float*)d_in[7];
    const float* wc  = (const float*)d_in[8];
    const float* bc  = (const float*)d_in[9];

    float* outp = (float*)d_out;
    float* tail = outp + (out_size - 512);   // ch_mask (1,64,4,2) after main out

    cudaFuncSetAttribute(conv_mma<false>,
                         cudaFuncAttributeMaxDynamicSharedMemorySize, SMEM_MMA);
    cudaFuncSetAttribute(conv_mma<true>,
                         cudaFuncAttributeMaxDynamicSharedMemorySize, SMEM_MMA);
    cudaFuncSetAttribute(final_mma,
                         cudaFuncAttributeMaxDynamicSharedMemorySize, SMEM_FIN);

    mask_kernel<<<1, 64>>>(gum, par, tail);
    prep_kernel<<<(4*9*Cn*Cn + 64*256 + 255)/256, 256>>>(w0, w1, w2, w3, wc);
    cvt_kernel<<<dim3(Hn, Bn), 256>>>(x0);

    dim3 grid(Hn, Bn);    // one CTA per (row, batch) = 2048 CTAs, 2/SM
    conv_mma<false><<<grid, 256, SMEM_MMA>>>(spa, 0);
    conv_mma<true ><<<grid, 256, SMEM_MMA>>>(spa, 1);
    conv_mma<true ><<<grid, 256, SMEM_MMA>>>(spa, 2);
    conv_mma<true ><<<grid, 256, SMEM_MMA>>>(spa, 3);

    final_mma<<<dim3(HWn/256, Bn), 512, SMEM_FIN>>>(bc, outp);
}

// round 16
// speedup vs baseline: 1.1030x; 1.1030x over previous
#include <cuda_runtime.h>
#include <cuda_fp16.h>
#include <math.h>
#include <stdint.h>

typedef unsigned long long u64;
typedef unsigned int u32;

#define Bn 16
#define Cn 64
#define Hn 128
#define Wn 128
#define HWn (Hn*Wn)
#define IMG (Cn*HWn)

// scratch
__device__ float g_md[4][Cn];
__device__ float g_ms[4][Cn];
// fp16 weights (single kind): [layer][tap][o*64+ci]
__device__ __half g_wt[4][9][Cn*Cn];
// fp16 wc for final 1x1: [o][k=256]
__device__ __half g_wc[64*256];
// fp16 NHWC features: input (converted x0) + 4 conv layer outputs
__device__ __half g16in[(u64)Bn*HWn*Cn];
__device__ __half g16[4][(u64)Bn*HWn*Cn];

// ---------------- smem layout for conv_mma (bytes) ---------------------------
// input: 3 halo rows (y-1,y,y+1), [row][xp 0..129][ci 0..63], 144B per xp
#define PX_XP_STRIDE 144
#define PX_ROW_STRIDE (130*PX_XP_STRIDE)       // 18720
#define OFF_PX 0
#define PX_BYTES (3*PX_ROW_STRIDE)             // 56160
// weights triple-buffered per-tap (single kind): [buf 0..2][o], 144B per o
#define OFF_W  PX_BYTES
#define W_O_STRIDE 144
#define W_BUF_STRIDE (64*W_O_STRIDE)           // 9216
#define OFF_MD  (OFF_W + 3*W_BUF_STRIDE)       // 83808
#define OFF_MS  (OFF_MD + 256)
#define OFF_MDH (OFF_MS + 256)
#define SMEM_MMA (OFF_MDH + 128)               // 84448  -> 2 CTAs/SM

// ---------------- smem layout for final_mma (bytes) --------------------------
#define FA_PX_STRIDE 144
#define FA_BUF_STRIDE (256*FA_PX_STRIDE)       // 36864
#define F_OFF_A 0
#define F_OFF_B (2*FA_BUF_STRIDE)              // 73728
#define FB_O_STRIDE 528
#define SMEM_FIN (F_OFF_B + 64*FB_O_STRIDE)    // 107520

// ---------------- warp-mma helpers (baseline PTX, no 'a' features) -----------
__device__ __forceinline__ void mma16816(float* c, const u32* a, u32 b0, u32 b1){
    asm("mma.sync.aligned.m16n8k16.row.col.f32.f16.f16.f32 "
        "{%0,%1,%2,%3},{%4,%5,%6,%7},{%8,%9},{%0,%1,%2,%3};"
        : "+f"(c[0]),"+f"(c[1]),"+f"(c[2]),"+f"(c[3])
        : "r"(a[0]),"r"(a[1]),"r"(a[2]),"r"(a[3]), "r"(b0),"r"(b1));
}
__device__ __forceinline__ void ldmat4(u32* r, u32 addr){
    asm volatile("ldmatrix.sync.aligned.m8n8.x4.shared.b16 {%0,%1,%2,%3},[%4];"
                 : "=r"(r[0]),"=r"(r[1]),"=r"(r[2]),"=r"(r[3]) : "r"(addr));
}
__device__ __forceinline__ u32 hmul2(u32 a, u32 b){
    u32 d; asm("mul.rn.f16x2 %0,%1,%2;" : "=r"(d) : "r"(a), "r"(b)); return d;
}
__device__ __forceinline__ void cp16(u32 dst, const void* src){
    asm volatile("cp.async.cg.shared.global [%0], [%1], 16;"
                 :: "r"(dst), "l"(src) : "memory");
}
__device__ __forceinline__ void cp_commit(){
    asm volatile("cp.async.commit_group;" ::: "memory");
}
template<int N>
__device__ __forceinline__ void cp_wait(){
    asm volatile("cp.async.wait_group %0;" :: "n"(N) : "memory");
}

// ---------------------------------------------------------------------------
// Gumbel-softmax channel mask
// ---------------------------------------------------------------------------
__global__ void mask_kernel(const float* __restrict__ gum,
                            const float* __restrict__ par,
                            float* __restrict__ out_tail)
{
    int c = threadIdx.x;
    if (c >= Cn) return;
#pragma unroll
    for (int l = 0; l < 4; ++l) {
        int i0 = c*8 + l*2;
        float g0 = -logf(-logf(gum[i0]));
        float g1 = -logf(-logf(gum[i0+1]));
        float l0 = par[i0]   + g0;
        float l1 = par[i0+1] + g1;
        float e  = expf(l1 - l0);
        float m0 = 1.0f/(1.0f+e);
        float m1 = e/(1.0f+e);
        g_md[l][c] = m0;
        g_ms[l][c] = m1;
        out_tail[i0]   = m0;
        out_tail[i0+1] = m1;
    }
}

// ---------------------------------------------------------------------------
// Weight prep: fp16 W per tap ([o][ci]) + fp16 wc for the final 1x1.
// ---------------------------------------------------------------------------
__global__ void prep_kernel(const float* __restrict__ w0, const float* __restrict__ w1,
                            const float* __restrict__ w2, const float* __restrict__ w3,
                            const float* __restrict__ wc)
{
    int idx = blockIdx.x*256 + threadIdx.x;
    if (idx < 4*9*Cn*Cn) {
        int l  = idx / (9*Cn*Cn);
        int r  = idx - l*(9*Cn*Cn);
        int t  = r / (Cn*Cn);
        int oc = r - t*(Cn*Cn);
        int ci = oc & 63;
        const float* ws = (l==0) ? w0 : (l==1) ? w1 : (l==2) ? w2 : w3;
        g_wt[l][t][oc] = __float2half(ws[(oc >> 6)*(Cn*9) + ci*9 + t]);
    } else {
        int i2 = idx - 4*9*Cn*Cn;
        if (i2 < 64*256) g_wc[i2] = __float2half(wc[i2]);
    }
}

// ---------------------------------------------------------------------------
// x0 NCHW fp32 -> NHWC fp16 (one image row per CTA)
// ---------------------------------------------------------------------------
__global__ void __launch_bounds__(256)
cvt_kernel(const float* __restrict__ x0)
{
    __shared__ __half s[128*65];
    const int y = blockIdx.x, b = blockIdx.y;
    const int tid = threadIdx.x;
#pragma unroll
    for (int it = 0; it < 32; ++it) {
        int idx = tid + it*256;
        int ci = idx >> 7, x = idx & 127;
        s[x*65 + ci] = __float2half(x0[(b*Cn + ci)*HWn + y*Wn + x]);
    }
    __syncthreads();
    __half* dst = g16in + ((u64)b*HWn + (u64)y*Wn)*Cn;
#pragma unroll
    for (int it = 0; it < 32; ++it) {
        int idx = tid + it*256;
        int x = idx >> 6, ci = idx & 63;
        dst[(u64)x*Cn + ci] = s[x*65 + ci];
    }
}

// ---------------------------------------------------------------------------
// Warp-MMA conv layer: mma.sync m16n8k16 fp16. Single weight kind W; the
// dual (dense) path is computed by scaling A fragments per-K with md:
//   D = (A.diag(md_k)) x W^T, Am = hmul2(Ah, md2_frag) in registers.
// 256-thread CTA, one output row, triple-buffered per-tap weights (9.2 KB),
// 2 CTAs/SM. One __syncthreads per tap.
//  DUAL=false: out = relu( F * (ms_o*spa + md_o) )
//  DUAL=true : out = relu( D * md_o*(1-spa) + F*spa )
// ---------------------------------------------------------------------------
template<bool DUAL>
__global__ void __launch_bounds__(256, 2)
conv_mma(const float* __restrict__ spa, int layer)
{
    extern __shared__ __align__(128) char sm[];
    const u32 smb  = (u32)__cvta_generic_to_shared(sm);
    const int tid  = threadIdx.x;
    const int lane = tid & 31;
    const int wid  = tid >> 5;

    const int y = blockIdx.x;
    const int b = blockIdx.y;

    float*  s_md  = (float*)(sm + OFF_MD);
    float*  s_ms  = (float*)(sm + OFF_MS);
    __half* s_mdh = (__half*)(sm + OFF_MDH);
    if (tid < Cn) {
        float md = g_md[layer][tid];
        s_md[tid]  = md;
        s_ms[tid]  = g_ms[layer][tid];
        s_mdh[tid] = __float2half(md);
    }

    // weight stager: tap t -> buffer t%3 (512 x 16B cp.async chunks)
    auto stageW = [&](int t){
        const u32 dst0 = smb + OFF_W + (u32)(t % 3)*W_BUF_STRIDE;
#pragma unroll
        for (int it = 0; it < 2; ++it) {
            int idx = tid + it*256;          // 512 chunks: 64 o x 8 seg
            int o = idx >> 3, seg = idx & 7;
            cp16(dst0 + (u32)(o*W_O_STRIDE + seg*16),
                 (const char*)&g_wt[layer][t][0] + o*128 + seg*16);
        }
        cp_commit();
    };

    stageW(0);   // group: W0

    // ---- stage input: 3 halo rows (y-1..y+1), fp16 NHWC via cp.async -------
    {
        const __half* src16 = (layer == 0)
            ? (g16in + (u64)b*((u64)HWn*Cn))
            : (g16[layer-1] + (u64)b*((u64)HWn*Cn));
        if (tid < 96) {        // zero x-halo columns (xp=0, xp=129) x 3 rows
            int r = tid / 32, col = (tid >> 4) & 1, i = tid & 15;
            *(u64*)(sm + OFF_PX + r*PX_ROW_STRIDE
                    + (col ? 129*PX_XP_STRIDE : 0) + i*8) = 0;
        }
#pragma unroll
        for (int r = 0; r < 3; ++r) {
            const int yy = y - 1 + r;
            if ((unsigned)yy < Hn) {
                const __half* rowsrc = src16 + (u64)yy*Wn*Cn;
#pragma unroll
                for (int it = 0; it < 4; ++it) {
                    int idx = tid + it*256;        // 1024 chunks: 128px x 8seg
                    int px = idx >> 3, seg = idx & 7;
                    cp16(smb + OFF_PX + (u32)(r*PX_ROW_STRIDE
                             + (px+1)*PX_XP_STRIDE + seg*16),
                         (const char*)(rowsrc + px*Cn) + seg*16);
                }
            } else {
#pragma unroll 1
                for (int i = tid; i < 130*16; i += 256)
                    *(u64*)(sm + OFF_PX + r*PX_ROW_STRIDE
                            + (i >> 4)*PX_XP_STRIDE + (i & 15)*8) = 0;
            }
        }
        cp_commit();   // group: A
    }
    stageW(1);         // group: W1

    // warp tile: mq = M quarter (32 px), nq = N half (32 och)
    const int mq    = wid & 3;
    const int nq    = wid >> 2;
    const int xbase = mq << 5;
    const int obase = nq << 5;

    const u32 a_lane = (u32)((lane & 15)*PX_XP_STRIDE + ((lane >> 4) << 4));
    const int lrow = lane & 7, lgrp = lane >> 3;
    const u32 b_lane = (u32)(((lgrp >> 1)*8 + lrow)*W_O_STRIDE + (lgrp & 1)*16);

    float accF[2][4][4], accD[2][4][4];
#pragma unroll
    for (int mt = 0; mt < 2; ++mt)
#pragma unroll
        for (int n = 0; n < 4; ++n)
#pragma unroll
            for (int j = 0; j < 4; ++j) {
                accF[mt][n][j] = 0.f;
                if (DUAL) accD[mt][n][j] = 0.f;
            }

    // md2 fragment regs (loaded after first sync below)
    u32 mdlo[4], mdhi[4];
    const int kbase = (lane & 3)*2;

#pragma unroll 1
    for (int t = 0; t < 9; ++t) {
        // pending: [Wt, (A if t==0), Wt+1] -> wait Wt (+A)
        if (t < 8) cp_wait<1>(); else cp_wait<0>();
        __syncthreads();
        if (t == 0 && DUAL) {
#pragma unroll
            for (int kk = 0; kk < 4; ++kk) {
                mdlo[kk] = *(const u32*)(s_mdh + kk*16 + kbase);
                mdhi[kk] = *(const u32*)(s_mdh + kk*16 + kbase + 8);
            }
        }
        if (t < 7) stageW(t + 2);   // writes buf (t+2)%3 == (t-1)%3: its
                                    // readers finished before the sync above

        const int ky = t/3, kx = t - (t/3)*3;
        const u32 abase = smb + OFF_PX
                        + (u32)(ky*PX_ROW_STRIDE)
                        + (u32)((kx + xbase)*PX_XP_STRIDE)
                        + a_lane;
        const u32 wbase = smb + OFF_W + (u32)(t % 3)*W_BUF_STRIDE
                        + (u32)(obase*W_O_STRIDE) + b_lane;

#pragma unroll
        for (int kk = 0; kk < 4; ++kk) {
            u32 Ah[2][4], Am[2][4];
            ldmat4(Ah[0], abase + kk*32);
            ldmat4(Ah[1], abase + 16*PX_XP_STRIDE + kk*32);
            if (DUAL) {
#pragma unroll
                for (int mt = 0; mt < 2; ++mt) {
                    Am[mt][0] = hmul2(Ah[mt][0], mdlo[kk]);
                    Am[mt][1] = hmul2(Ah[mt][1], mdlo[kk]);
                    Am[mt][2] = hmul2(Ah[mt][2], mdhi[kk]);
                    Am[mt][3] = hmul2(Ah[mt][3], mdhi[kk]);
                }
            }
#pragma unroll
            for (int ntp = 0; ntp < 2; ++ntp) {
                const u32 wb = wbase + (u32)(ntp*16*W_O_STRIDE + kk*32);
                const int n0 = ntp*2, n1 = n0 + 1;
                u32 Bh[4];
                ldmat4(Bh, wb);
                mma16816(accF[0][n0], Ah[0], Bh[0], Bh[1]);
                mma16816(accF[0][n1], Ah[0], Bh[2], Bh[3]);
                mma16816(accF[1][n0], Ah[1], Bh[0], Bh[1]);
                mma16816(accF[1][n1], Ah[1], Bh[2], Bh[3]);
                if (DUAL) {
                    mma16816(accD[0][n0], Am[0], Bh[0], Bh[1]);
                    mma16816(accD[0][n1], Am[0], Bh[2], Bh[3]);
                    mma16816(accD[1][n0], Am[1], Bh[0], Bh[1]);
                    mma16816(accD[1][n1], Am[1], Bh[2], Bh[3]);
                }
            }
        }
    }

    // ---- fused gate + ReLU epilogue: fp16 NHWC ----
    const int g  = lane >> 2;
    const int t4 = lane & 3;
    __half* o16 = g16[layer] + ((u64)b*HWn + (u64)y*Wn)*Cn;

#pragma unroll
    for (int mt = 0; mt < 2; ++mt) {
        const int xA = xbase + mt*16 + g;
        const int xB = xA + 8;
        const float spA = spa[b*HWn + y*Wn + xA];
        const float spB = spa[b*HWn + y*Wn + xB];
#pragma unroll
        for (int nt = 0; nt < 4; ++nt) {
            const int o0 = obase + nt*8 + 2*t4, o1 = o0 + 1;
            float r0, r1, r2, r3;
            if (!DUAL) {
                r0 = accF[mt][nt][0] * (s_ms[o0]*spA + s_md[o0]);
                r1 = accF[mt][nt][1] * (s_ms[o1]*spA + s_md[o1]);
                r2 = accF[mt][nt][2] * (s_ms[o0]*spB + s_md[o0]);
                r3 = accF[mt][nt][3] * (s_ms[o1]*spB + s_md[o1]);
            } else {
                r0 = accD[mt][nt][0]*s_md[o0]*(1.f-spA) + accF[mt][nt][0]*spA;
                r1 = accD[mt][nt][1]*s_md[o1]*(1.f-spA) + accF[mt][nt][1]*spA;
                r2 = accD[mt][nt][2]*s_md[o0]*(1.f-spB) + accF[mt][nt][2]*spB;
                r3 = accD[mt][nt][3]*s_md[o1]*(1.f-spB) + accF[mt][nt][3]*spB;
            }
            r0 = fmaxf(r0, 0.f); r1 = fmaxf(r1, 0.f);
            r2 = fmaxf(r2, 0.f); r3 = fmaxf(r3, 0.f);
            *(__half2*)(o16 + (u64)xA*Cn + o0) = __floats2half2_rn(r0, r1);
            *(__half2*)(o16 + (u64)xB*Cn + o0) = __floats2half2_rn(r2, r3);
        }
    }
}

// ---------------------------------------------------------------------------
// Final 1x1 conv on tensor cores: M=256 px, N=64, K=256 (4 NHWC layers).
// ---------------------------------------------------------------------------
__global__ void __launch_bounds__(512, 1)
final_mma(const float* __restrict__ bc, float* __restrict__ outp)
{
    extern __shared__ __align__(128) char sm[];
    const u32 smb  = (u32)__cvta_generic_to_shared(sm);
    const int tid  = threadIdx.x;
    const int lane = tid & 31;
    const int wid  = tid >> 5;

    const int px0 = blockIdx.x * 256;
    const int b   = blockIdx.y;

#pragma unroll
    for (int it = 0; it < 4; ++it) {
        int idx = tid + it*512;
        int o = idx >> 5, seg = idx & 31;
        cp16(smb + F_OFF_B + (u32)(o*FB_O_STRIDE + seg*16),
             (const char*)(g_wc + o*256) + seg*16);
    }
    cp_commit();

    auto stageA = [&](int l, int bi){
        const __half* src = g16[l] + ((u64)b*HWn + (u64)px0)*Cn;
        const u32 dst = smb + F_OFF_A + (u32)bi*FA_BUF_STRIDE;
#pragma unroll
        for (int it = 0; it < 4; ++it) {
            int idx = tid + it*512;
            int px = idx >> 3, seg = idx & 7;
            cp16(dst + (u32)(px*FA_PX_STRIDE + seg*16),
                 (const char*)(src + (u64)px*Cn) + seg*16);
        }
        cp_commit();
    };
    stageA(0, 0);

    const int mq = wid & 7;
    const int nq = wid >> 3;
    const int obase = nq << 5;

    const u32 a_lane = (u32)((lane & 15)*FA_PX_STRIDE + ((lane >> 4) << 4));
    const int lrow = lane & 7, lgrp = lane >> 3;
    const u32 b_lane = (u32)(((lgrp >> 1)*8 + lrow)*FB_O_STRIDE + (lgrp & 1)*16);

    float acc[2][4][4];
#pragma unroll
    for (int mt = 0; mt < 2; ++mt)
#pragma unroll
        for (int n = 0; n < 4; ++n)
#pragma unroll
            for (int j = 0; j < 4; ++j) acc[mt][n][j] = 0.f;

#pragma unroll 1
    for (int l = 0; l < 4; ++l) {
        const int bi = l & 1;
        if (l < 3) stageA(l+1, bi^1);
        if (l < 3) cp_wait<1>(); else cp_wait<0>();
        __syncthreads();

        const u32 abase = smb + F_OFF_A + (u32)bi*FA_BUF_STRIDE
                        + (u32)(mq*32*FA_PX_STRIDE) + a_lane;
        const u32 wbase = smb + F_OFF_B + (u32)(obase*FB_O_STRIDE)
                        + (u32)(l*128) + b_lane;
#pragma unroll
        for (int kk = 0; kk < 4; ++kk) {
            u32 Ah[2][4];
            ldmat4(Ah[0], abase + kk*32);
            ldmat4(Ah[1], abase + 16*FA_PX_STRIDE + kk*32);
#pragma unroll
            for (int ntp = 0; ntp < 2; ++ntp) {
                const u32 wb = wbase + (u32)(ntp*16*FB_O_STRIDE + kk*32);
                const int n0 = ntp*2, n1 = n0 + 1;
                u32 Bh[4];
                ldmat4(Bh, wb);
                mma16816(acc[0][n0], Ah[0], Bh[0], Bh[1]);
                mma16816(acc[0][n1], Ah[0], Bh[2], Bh[3]);
                mma16816(acc[1][n0], Ah[1], Bh[0], Bh[1]);
                mma16816(acc[1][n1], Ah[1], Bh[2], Bh[3]);
            }
        }
        __syncthreads();
    }

    const int g  = lane >> 2;
    const int t4 = lane & 3;
    float* ob = outp + (u64)b*IMG + px0;

#pragma unroll
    for (int mt = 0; mt < 2; ++mt) {
        const int xA = mq*32 + mt*16 + g;
        const int xB = xA + 8;
#pragma unroll
        for (int nt = 0; nt < 4; ++nt) {
            const int o0 = obase + nt*8 + 2*t4, o1 = o0 + 1;
            ob[o0*HWn + xA] = acc[mt][nt][0] + bc[o0];
            ob[o1*HWn + xA] = acc[mt][nt][1] + bc[o1];
            ob[o0*HWn + xB] = acc[mt][nt][2] + bc[o0];
            ob[o1*HWn + xB] = acc[mt][nt][3] + bc[o1];
        }
    }
}

// ---------------------------------------------------------------------------
extern "C" void kernel_launch(void* const* d_in, const int* in_sizes, int n_in,
                              void* d_out, int out_size)
{
    const float* x0  = (const float*)d_in[0];
    const float* spa = (const float*)d_in[1];
    const float* gum = (const float*)d_in[2];
    const float* par = (const float*)d_in[3];
    const float* w0  = (const float*)d_in[4];
    const float* w1  = (const float*)d_in[5];
    const float* w2  = (const float*)d_in[6];
    const float* w3  = (const float*)d_in[7];
    const float* wc  = (const float*)d_in[8];
    const float* bc  = (const float*)d_in[9];

    float* outp = (float*)d_out;
    float* tail = outp + (out_size - 512);   // ch_mask (1,64,4,2) after main out

    cudaFuncSetAttribute(conv_mma<false>,
                         cudaFuncAttributeMaxDynamicSharedMemorySize, SMEM_MMA);
    cudaFuncSetAttribute(conv_mma<true>,
                         cudaFuncAttributeMaxDynamicSharedMemorySize, SMEM_MMA);
    cudaFuncSetAttribute(final_mma,
                         cudaFuncAttributeMaxDynamicSharedMemorySize, SMEM_FIN);

    mask_kernel<<<1, 64>>>(gum, par, tail);
    prep_kernel<<<(4*9*Cn*Cn + 64*256 + 255)/256, 256>>>(w0, w1, w2, w3, wc);
    cvt_kernel<<<dim3(Hn, Bn), 256>>>(x0);

    dim3 grid(Hn, Bn);    // one CTA per (row, batch) = 2048 CTAs, 2/SM
    conv_mma<false><<<grid, 256, SMEM_MMA>>>(spa, 0);
    conv_mma<true ><<<grid, 256, SMEM_MMA>>>(spa, 1);
    conv_mma<true ><<<grid, 256, SMEM_MMA>>>(spa, 2);
    conv_mma<true ><<<grid, 256, SMEM_MMA>>>(spa, 3);

    final_mma<<<dim3(HWn/256, Bn), 512, SMEM_FIN>>>(bc, outp);
}

// round 17
// speedup vs baseline: 1.1444x; 1.0375x over previous
#include <cuda_runtime.h>
#include <cuda_fp16.h>
#include <math.h>
#include <stdint.h>

typedef unsigned long long u64;
typedef unsigned int u32;

#define Bn 16
#define Cn 64
#define Hn 128
#define Wn 128
#define HWn (Hn*Wn)
#define IMG (Cn*HWn)

// scratch
__device__ float g_md[4][Cn];
__device__ float g_ms[4][Cn];
// fp16 weights (single kind): [layer][tap][o*64+ci]
__device__ __half g_wt[4][9][Cn*Cn];
// fp16 wc for final 1x1: [o][k=256]
__device__ __half g_wc[64*256];
// fp16 NHWC features: input (converted x0) + 4 conv layer outputs
__device__ __half g16in[(u64)Bn*HWn*Cn];
__device__ __half g16[4][(u64)Bn*HWn*Cn];

// ---------------- smem layout for conv_mma (bytes) ---------------------------
// input: 3 halo rows (y-1,y,y+1), [row][xp 0..129][ci 0..63], 144B per xp
#define PX_XP_STRIDE 144
#define PX_ROW_STRIDE (130*PX_XP_STRIDE)       // 18720
#define OFF_PX 0
#define PX_BYTES (3*PX_ROW_STRIDE)             // 56160
// weights double-buffered per-ky (3 taps each): [buf 0..1][kx 0..2][o]
#define OFF_W  PX_BYTES
#define W_O_STRIDE 144
#define W_KX_STRIDE (64*W_O_STRIDE)            // 9216
#define W_BUF_STRIDE (3*W_KX_STRIDE)           // 27648
#define OFF_MD  (OFF_W + 2*W_BUF_STRIDE)       // 111456
#define OFF_MS  (OFF_MD + 256)
#define OFF_MDH (OFF_MS + 256)
#define SMEM_MMA (OFF_MDH + 128)               // 112096 -> 2 CTAs/SM (224 KB)

// ---------------- smem layout for final_mma (bytes) --------------------------
#define FA_PX_STRIDE 144
#define FA_BUF_STRIDE (256*FA_PX_STRIDE)       // 36864
#define F_OFF_A 0
#define F_OFF_B (2*FA_BUF_STRIDE)              // 73728
#define FB_O_STRIDE 528
#define SMEM_FIN (F_OFF_B + 64*FB_O_STRIDE)    // 107520

// ---------------- warp-mma helpers (baseline PTX, no 'a' features) -----------
__device__ __forceinline__ void mma16816(float* c, const u32* a, u32 b0, u32 b1){
    asm("mma.sync.aligned.m16n8k16.row.col.f32.f16.f16.f32 "
        "{%0,%1,%2,%3},{%4,%5,%6,%7},{%8,%9},{%0,%1,%2,%3};"
        : "+f"(c[0]),"+f"(c[1]),"+f"(c[2]),"+f"(c[3])
        : "r"(a[0]),"r"(a[1]),"r"(a[2]),"r"(a[3]), "r"(b0),"r"(b1));
}
__device__ __forceinline__ void ldmat4(u32* r, u32 addr){
    asm volatile("ldmatrix.sync.aligned.m8n8.x4.shared.b16 {%0,%1,%2,%3},[%4];"
                 : "=r"(r[0]),"=r"(r[1]),"=r"(r[2]),"=r"(r[3]) : "r"(addr));
}
__device__ __forceinline__ u32 hmul2(u32 a, u32 b){
    u32 d; asm("mul.rn.f16x2 %0,%1,%2;" : "=r"(d) : "r"(a), "r"(b)); return d;
}
__device__ __forceinline__ void cp16(u32 dst, const void* src){
    asm volatile("cp.async.cg.shared.global [%0], [%1], 16;"
                 :: "r"(dst), "l"(src) : "memory");
}
__device__ __forceinline__ void cp_commit(){
    asm volatile("cp.async.commit_group;" ::: "memory");
}
template<int N>
__device__ __forceinline__ void cp_wait(){
    asm volatile("cp.async.wait_group %0;" :: "n"(N) : "memory");
}

// ---------------------------------------------------------------------------
// Gumbel-softmax channel mask
// ---------------------------------------------------------------------------
__global__ void mask_kernel(const float* __restrict__ gum,
                            const float* __restrict__ par,
                            float* __restrict__ out_tail)
{
    int c = threadIdx.x;
    if (c >= Cn) return;
#pragma unroll
    for (int l = 0; l < 4; ++l) {
        int i0 = c*8 + l*2;
        float g0 = -logf(-logf(gum[i0]));
        float g1 = -logf(-logf(gum[i0+1]));
        float l0 = par[i0]   + g0;
        float l1 = par[i0+1] + g1;
        float e  = expf(l1 - l0);
        float m0 = 1.0f/(1.0f+e);
        float m1 = e/(1.0f+e);
        g_md[l][c] = m0;
        g_ms[l][c] = m1;
        out_tail[i0]   = m0;
        out_tail[i0+1] = m1;
    }
}

// ---------------------------------------------------------------------------
// Weight prep: fp16 W per tap ([o][ci]) + fp16 wc for the final 1x1.
// ---------------------------------------------------------------------------
__global__ void prep_kernel(const float* __restrict__ w0, const float* __restrict__ w1,
                            const float* __restrict__ w2, const float* __restrict__ w3,
                            const float* __restrict__ wc)
{
    int idx = blockIdx.x*256 + threadIdx.x;
    if (idx < 4*9*Cn*Cn) {
        int l  = idx / (9*Cn*Cn);
        int r  = idx - l*(9*Cn*Cn);
        int t  = r / (Cn*Cn);
        int oc = r - t*(Cn*Cn);
        int ci = oc & 63;
        const float* ws = (l==0) ? w0 : (l==1) ? w1 : (l==2) ? w2 : w3;
        g_wt[l][t][oc] = __float2half(ws[(oc >> 6)*(Cn*9) + ci*9 + t]);
    } else {
        int i2 = idx - 4*9*Cn*Cn;
        if (i2 < 64*256) g_wc[i2] = __float2half(wc[i2]);
    }
}

// ---------------------------------------------------------------------------
// x0 NCHW fp32 -> NHWC fp16 (one image row per CTA)
// ---------------------------------------------------------------------------
__global__ void __launch_bounds__(256)
cvt_kernel(const float* __restrict__ x0)
{
    __shared__ __half s[128*65];
    const int y = blockIdx.x, b = blockIdx.y;
    const int tid = threadIdx.x;
#pragma unroll
    for (int it = 0; it < 32; ++it) {
        int idx = tid + it*256;
        int ci = idx >> 7, x = idx & 127;
        s[x*65 + ci] = __float2half(x0[(b*Cn + ci)*HWn + y*Wn + x]);
    }
    __syncthreads();
    __half* dst = g16in + ((u64)b*HWn + (u64)y*Wn)*Cn;
#pragma unroll
    for (int it = 0; it < 32; ++it) {
        int idx = tid + it*256;
        int x = idx >> 6, ci = idx & 63;
        dst[(u64)x*Cn + ci] = s[x*65 + ci];
    }
}

// ---------------------------------------------------------------------------
// Warp-MMA conv layer: mma.sync m16n8k16 fp16, single weight kind; dual path
// via A-fragment scaling (Am = Ah * md_k). Per-ky weight staging (3 taps,
// double-buffered) -> 3 barriers per CTA, 192 dual-MMAs/warp per barrier.
// 256-thread CTA, one output row, 2 CTAs/SM.
//  DUAL=false: out = relu( F * (ms_o*spa + md_o) )
//  DUAL=true : out = relu( D * md_o*(1-spa) + F*spa )
// ---------------------------------------------------------------------------
template<bool DUAL>
__global__ void __launch_bounds__(256, 2)
conv_mma(const float* __restrict__ spa, int layer)
{
    extern __shared__ __align__(128) char sm[];
    const u32 smb  = (u32)__cvta_generic_to_shared(sm);
    const int tid  = threadIdx.x;
    const int lane = tid & 31;
    const int wid  = tid >> 5;

    const int y = blockIdx.x;
    const int b = blockIdx.y;

    float*  s_md  = (float*)(sm + OFF_MD);
    float*  s_ms  = (float*)(sm + OFF_MS);
    __half* s_mdh = (__half*)(sm + OFF_MDH);
    if (tid < Cn) {
        float md = g_md[layer][tid];
        s_md[tid]  = md;
        s_ms[tid]  = g_ms[layer][tid];
        s_mdh[tid] = __float2half(md);
    }

    // weight stager: ky row (3 taps) -> buffer bi (1536 x 16B cp.async chunks)
    auto stageW3 = [&](int ky, int bi){
        const u32 dst0 = smb + OFF_W + (u32)bi*W_BUF_STRIDE;
#pragma unroll
        for (int it = 0; it < 6; ++it) {
            int idx = tid + it*256;          // kx(3) x o(64) x seg(8)
            int kx = idx >> 9, rem = idx & 511;
            int o = rem >> 3, seg = rem & 7;
            cp16(dst0 + (u32)(kx*W_KX_STRIDE + o*W_O_STRIDE + seg*16),
                 (const char*)&g_wt[layer][3*ky+kx][0] + o*128 + seg*16);
        }
        cp_commit();
    };

    stageW3(0, 0);   // group: W0

    // ---- stage input: 3 halo rows (y-1..y+1), fp16 NHWC via cp.async -------
    {
        const __half* src16 = (layer == 0)
            ? (g16in + (u64)b*((u64)HWn*Cn))
            : (g16[layer-1] + (u64)b*((u64)HWn*Cn));
        if (tid < 96) {        // zero x-halo columns (xp=0, xp=129) x 3 rows
            int r = tid / 32, col = (tid >> 4) & 1, i = tid & 15;
            *(u64*)(sm + OFF_PX + r*PX_ROW_STRIDE
                    + (col ? 129*PX_XP_STRIDE : 0) + i*8) = 0;
        }
#pragma unroll
        for (int r = 0; r < 3; ++r) {
            const int yy = y - 1 + r;
            if ((unsigned)yy < Hn) {
                const __half* rowsrc = src16 + (u64)yy*Wn*Cn;
#pragma unroll
                for (int it = 0; it < 4; ++it) {
                    int idx = tid + it*256;        // 1024 chunks: 128px x 8seg
                    int px = idx >> 3, seg = idx & 7;
                    cp16(smb + OFF_PX + (u32)(r*PX_ROW_STRIDE
                             + (px+1)*PX_XP_STRIDE + seg*16),
                         (const char*)(rowsrc + px*Cn) + seg*16);
                }
            } else {
#pragma unroll 1
                for (int i = tid; i < 130*16; i += 256)
                    *(u64*)(sm + OFF_PX + r*PX_ROW_STRIDE
                            + (i >> 4)*PX_XP_STRIDE + (i & 15)*8) = 0;
            }
        }
        cp_commit();   // group: A
    }
    stageW3(1, 1);     // group: W1

    // warp tile: mq = M quarter (32 px), nq = N half (32 och)
    const int mq    = wid & 3;
    const int nq    = wid >> 2;
    const int xbase = mq << 5;
    const int obase = nq << 5;

    const u32 a_lane = (u32)((lane & 15)*PX_XP_STRIDE + ((lane >> 4) << 4));
    const int lrow = lane & 7, lgrp = lane >> 3;
    const u32 b_lane = (u32)(((lgrp >> 1)*8 + lrow)*W_O_STRIDE + (lgrp & 1)*16);

    float accF[2][4][4], accD[2][4][4];
#pragma unroll
    for (int mt = 0; mt < 2; ++mt)
#pragma unroll
        for (int n = 0; n < 4; ++n)
#pragma unroll
            for (int j = 0; j < 4; ++j) {
                accF[mt][n][j] = 0.f;
                if (DUAL) accD[mt][n][j] = 0.f;
            }

    // md2 fragment regs (per-lane K mapping of the m16n8k16 A fragment)
    u32 mdlo[4], mdhi[4];
    const int kbase = (lane & 3)*2;

#pragma unroll 1
    for (int ky = 0; ky < 3; ++ky) {
        // pending before wait: ky0: [W0, A, W1] -> wait<1>; ky1: [W1] -> wait<0>;
        // ky2: [W2] -> wait<0>
        if (ky == 0) cp_wait<1>(); else cp_wait<0>();
        __syncthreads();
        if (ky == 0 && DUAL) {
#pragma unroll
            for (int kk = 0; kk < 4; ++kk) {
                mdlo[kk] = *(const u32*)(s_mdh + kk*16 + kbase);
                mdhi[kk] = *(const u32*)(s_mdh + kk*16 + kbase + 8);
            }
        }
        // refill buf0 with ky=2 weights; safe: ky0 readers done (sync above)
        if (ky == 1) stageW3(2, 0);

        const u32 arow  = smb + OFF_PX + (u32)(ky*PX_ROW_STRIDE)
                        + (u32)(xbase*PX_XP_STRIDE) + a_lane;
        const u32 wb_ky = smb + OFF_W + (u32)((ky & 1)*W_BUF_STRIDE)
                        + (u32)(obase*W_O_STRIDE) + b_lane;

#pragma unroll
        for (int kx = 0; kx < 3; ++kx) {
            const u32 abase = arow  + (u32)(kx*PX_XP_STRIDE);
            const u32 wbase = wb_ky + (u32)(kx*W_KX_STRIDE);
#pragma unroll
            for (int kk = 0; kk < 4; ++kk) {
                u32 Ah[2][4], Am[2][4];
                ldmat4(Ah[0], abase + kk*32);
                ldmat4(Ah[1], abase + 16*PX_XP_STRIDE + kk*32);
                if (DUAL) {
#pragma unroll
                    for (int mt = 0; mt < 2; ++mt) {
                        Am[mt][0] = hmul2(Ah[mt][0], mdlo[kk]);
                        Am[mt][1] = hmul2(Ah[mt][1], mdlo[kk]);
                        Am[mt][2] = hmul2(Ah[mt][2], mdhi[kk]);
                        Am[mt][3] = hmul2(Ah[mt][3], mdhi[kk]);
                    }
                }
#pragma unroll
                for (int ntp = 0; ntp < 2; ++ntp) {
                    const u32 wb = wbase + (u32)(ntp*16*W_O_STRIDE + kk*32);
                    const int n0 = ntp*2, n1 = n0 + 1;
                    u32 Bh[4];
                    ldmat4(Bh, wb);
                    mma16816(accF[0][n0], Ah[0], Bh[0], Bh[1]);
                    mma16816(accF[0][n1], Ah[0], Bh[2], Bh[3]);
                    mma16816(accF[1][n0], Ah[1], Bh[0], Bh[1]);
                    mma16816(accF[1][n1], Ah[1], Bh[2], Bh[3]);
                    if (DUAL) {
                        mma16816(accD[0][n0], Am[0], Bh[0], Bh[1]);
                        mma16816(accD[0][n1], Am[0], Bh[2], Bh[3]);
                        mma16816(accD[1][n0], Am[1], Bh[0], Bh[1]);
                        mma16816(accD[1][n1], Am[1], Bh[2], Bh[3]);
                    }
                }
            }
        }
    }

    // ---- fused gate + ReLU epilogue: fp16 NHWC ----
    const int g  = lane >> 2;
    const int t4 = lane & 3;
    __half* o16 = g16[layer] + ((u64)b*HWn + (u64)y*Wn)*Cn;

#pragma unroll
    for (int mt = 0; mt < 2; ++mt) {
        const int xA = xbase + mt*16 + g;
        const int xB = xA + 8;
        const float spA = spa[b*HWn + y*Wn + xA];
        const float spB = spa[b*HWn + y*Wn + xB];
#pragma unroll
        for (int nt = 0; nt < 4; ++nt) {
            const int o0 = obase + nt*8 + 2*t4, o1 = o0 + 1;
            float r0, r1, r2, r3;
            if (!DUAL) {
                r0 = accF[mt][nt][0] * (s_ms[o0]*spA + s_md[o0]);
                r1 = accF[mt][nt][1] * (s_ms[o1]*spA + s_md[o1]);
                r2 = accF[mt][nt][2] * (s_ms[o0]*spB + s_md[o0]);
                r3 = accF[mt][nt][3] * (s_ms[o1]*spB + s_md[o1]);
            } else {
                r0 = accD[mt][nt][0]*s_md[o0]*(1.f-spA) + accF[mt][nt][0]*spA;
                r1 = accD[mt][nt][1]*s_md[o1]*(1.f-spA) + accF[mt][nt][1]*spA;
                r2 = accD[mt][nt][2]*s_md[o0]*(1.f-spB) + accF[mt][nt][2]*spB;
                r3 = accD[mt][nt][3]*s_md[o1]*(1.f-spB) + accF[mt][nt][3]*spB;
            }
            r0 = fmaxf(r0, 0.f); r1 = fmaxf(r1, 0.f);
            r2 = fmaxf(r2, 0.f); r3 = fmaxf(r3, 0.f);
            *(__half2*)(o16 + (u64)xA*Cn + o0) = __floats2half2_rn(r0, r1);
            *(__half2*)(o16 + (u64)xB*Cn + o0) = __floats2half2_rn(r2, r3);
        }
    }
}

// ---------------------------------------------------------------------------
// Final 1x1 conv on tensor cores: M=256 px, N=64, K=256 (4 NHWC layers).
// ---------------------------------------------------------------------------
__global__ void __launch_bounds__(512, 1)
final_mma(const float* __restrict__ bc, float* __restrict__ outp)
{
    extern __shared__ __align__(128) char sm[];
    const u32 smb  = (u32)__cvta_generic_to_shared(sm);
    const int tid  = threadIdx.x;
    const int lane = tid & 31;
    const int wid  = tid >> 5;

    const int px0 = blockIdx.x * 256;
    const int b   = blockIdx.y;

#pragma unroll
    for (int it = 0; it < 4; ++it) {
        int idx = tid + it*512;
        int o = idx >> 5, seg = idx & 31;
        cp16(smb + F_OFF_B + (u32)(o*FB_O_STRIDE + seg*16),
             (const char*)(g_wc + o*256) + seg*16);
    }
    cp_commit();

    auto stageA = [&](int l, int bi){
        const __half* src = g16[l] + ((u64)b*HWn + (u64)px0)*Cn;
        const u32 dst = smb + F_OFF_A + (u32)bi*FA_BUF_STRIDE;
#pragma unroll
        for (int it = 0; it < 4; ++it) {
            int idx = tid + it*512;
            int px = idx >> 3, seg = idx & 7;
            cp16(dst + (u32)(px*FA_PX_STRIDE + seg*16),
                 (const char*)(src + (u64)px*Cn) + seg*16);
        }
        cp_commit();
    };
    stageA(0, 0);

    const int mq = wid & 7;
    const int nq = wid >> 3;
    const int obase = nq << 5;

    const u32 a_lane = (u32)((lane & 15)*FA_PX_STRIDE + ((lane >> 4) << 4));
    const int lrow = lane & 7, lgrp = lane >> 3;
    const u32 b_lane = (u32)(((lgrp >> 1)*8 + lrow)*FB_O_STRIDE + (lgrp & 1)*16);

    float acc[2][4][4];
#pragma unroll
    for (int mt = 0; mt < 2; ++mt)
#pragma unroll
        for (int n = 0; n < 4; ++n)
#pragma unroll
            for (int j = 0; j < 4; ++j) acc[mt][n][j] = 0.f;

#pragma unroll 1
    for (int l = 0; l < 4; ++l) {
        const int bi = l & 1;
        if (l < 3) stageA(l+1, bi^1);
        if (l < 3) cp_wait<1>(); else cp_wait<0>();
        __syncthreads();

        const u32 abase = smb + F_OFF_A + (u32)bi*FA_BUF_STRIDE
                        + (u32)(mq*32*FA_PX_STRIDE) + a_lane;
        const u32 wbase = smb + F_OFF_B + (u32)(obase*FB_O_STRIDE)
                        + (u32)(l*128) + b_lane;
#pragma unroll
        for (int kk = 0; kk < 4; ++kk) {
            u32 Ah[2][4];
            ldmat4(Ah[0], abase + kk*32);
            ldmat4(Ah[1], abase + 16*FA_PX_STRIDE + kk*32);
#pragma unroll
            for (int ntp = 0; ntp < 2; ++ntp) {
                const u32 wb = wbase + (u32)(ntp*16*FB_O_STRIDE + kk*32);
                const int n0 = ntp*2, n1 = n0 + 1;
                u32 Bh[4];
                ldmat4(Bh, wb);
                mma16816(acc[0][n0], Ah[0], Bh[0], Bh[1]);
                mma16816(acc[0][n1], Ah[0], Bh[2], Bh[3]);
                mma16816(acc[1][n0], Ah[1], Bh[0], Bh[1]);
                mma16816(acc[1][n1], Ah[1], Bh[2], Bh[3]);
            }
        }
        __syncthreads();
    }

    const int g  = lane >> 2;
    const int t4 = lane & 3;
    float* ob = outp + (u64)b*IMG + px0;

#pragma unroll
    for (int mt = 0; mt < 2; ++mt) {
        const int xA = mq*32 + mt*16 + g;
        const int xB = xA + 8;
#pragma unroll
        for (int nt = 0; nt < 4; ++nt) {
            const int o0 = obase + nt*8 + 2*t4, o1 = o0 + 1;
            ob[o0*HWn + xA] = acc[mt][nt][0] + bc[o0];
            ob[o1*HWn + xA] = acc[mt][nt][1] + bc[o1];
            ob[o0*HWn + xB] = acc[mt][nt][2] + bc[o0];
            ob[o1*HWn + xB] = acc[mt][nt][3] + bc[o1];
        }
    }
}

// ---------------------------------------------------------------------------
extern "C" void kernel_launch(void* const* d_in, const int* in_sizes, int n_in,
                              void* d_out, int out_size)
{
    const float* x0  = (const float*)d_in[0];
    const float* spa = (const float*)d_in[1];
    const float* gum = (const float*)d_in[2];
    const float* par = (const float*)d_in[3];
    const float* w0  = (const float*)d_in[4];
    const float* w1  = (const float*)d_in[5];
    const float* w2  = (const float*)d_in[6];
    const float* w3  = (const float*)d_in[7];
    const float* wc  = (const float*)d_in[8];
    const float* bc  = (const float*)d_in[9];

    float* outp = (float*)d_out;
    float* tail = outp + (out_size - 512);   // ch_mask (1,64,4,2) after main out

    cudaFuncSetAttribute(conv_mma<false>,
                         cudaFuncAttributeMaxDynamicSharedMemorySize, SMEM_MMA);
    cudaFuncSetAttribute(conv_mma<true>,
                         cudaFuncAttributeMaxDynamicSharedMemorySize, SMEM_MMA);
    cudaFuncSetAttribute(final_mma,
                         cudaFuncAttributeMaxDynamicSharedMemorySize, SMEM_FIN);

    mask_kernel<<<1, 64>>>(gum, par, tail);
    prep_kernel<<<(4*9*Cn*Cn + 64*256 + 255)/256, 256>>>(w0, w1, w2, w3, wc);
    cvt_kernel<<<dim3(Hn, Bn), 256>>>(x0);

    dim3 grid(Hn, Bn);    // one CTA per (row, batch) = 2048 CTAs, 2/SM
    conv_mma<false><<<grid, 256, SMEM_MMA>>>(spa, 0);
    conv_mma<true ><<<grid, 256, SMEM_MMA>>>(spa, 1);
    conv_mma<true ><<<grid, 256, SMEM_MMA>>>(spa, 2);
    conv_mma<true ><<<grid, 256, SMEM_MMA>>>(spa, 3);

    final_mma<<<dim3(HWn/256, Bn), 512, SMEM_FIN>>>(bc, outp);
}